// round 1
// baseline (speedup 1.0000x reference)
#include <cuda_runtime.h>

#define KBATCH 64
#define NN 1024
#define DIN 16
#define H1D 4
#define DOUT 8
#define FC1D 54

// ---------------- scratch (static device memory; no allocation) ----------------
__device__ unsigned g_adjT[NN * 32];          // transposed bit mask: word (i,l) bit jj = adj[i][jj*32+l]
__device__ float4   g_h1[KBATCH * NN];        // layer1 h  [K][N][4]
__device__ float2   g_f1p1[KBATCH * NN];      // {e^f1, e^{0.01 f1}}
__device__ float2   g_f2p1[KBATCH * NN];      // {e^f2, e^{0.01 f2}}
__device__ float4   g_h1o[KBATCH * NN];       // relu(gat1) [K][N][4]
__device__ float4   g_h2[KBATCH * NN * 2];    // layer2 h [K][N][8]
__device__ float2   g_f1p2[KBATCH * NN];
__device__ float2   g_f2p2[KBATCH * NN];
__device__ float4   g_g4[KBATCH * NN * 2];    // relu(gat2) [K][N][8] == [K][8192]
__device__ float    g_x[KBATCH * FC1D];       // fc1 accumulator

// ---------------- 1. pack adjacency into transposed bitmask ----------------
__global__ void pack_adj_kernel(const int* __restrict__ adj) {
    int warp = threadIdx.x >> 5, lane = threadIdx.x & 31;
    int i = blockIdx.x * 8 + warp;
    unsigned acc = 0;
#pragma unroll
    for (int jj = 0; jj < 32; jj++) {
        int v = adj[i * NN + jj * 32 + lane];
        acc |= (v > 0 ? 1u : 0u) << jj;
    }
    g_adjT[i * 32 + lane] = acc;
}

// ---------------- 2. layer-1 projection + exp precompute ----------------
__global__ void prep1_kernel(const float* __restrict__ X,
                             const float* __restrict__ W1,
                             const float* __restrict__ a1) {
    __shared__ float w[DIN * H1D];
    __shared__ float a[2 * H1D];
    int t = threadIdx.x;
    if (t < DIN * H1D) w[t] = W1[t];
    if (t < 2 * H1D) a[t] = a1[t];
    __syncthreads();
    int kn = blockIdx.x * 256 + t;
    const float4* x4 = reinterpret_cast<const float4*>(X) + kn * 4;
    float h[H1D] = {0.f, 0.f, 0.f, 0.f};
#pragma unroll
    for (int q = 0; q < 4; q++) {
        float4 xv = x4[q];
        float xs[4] = {xv.x, xv.y, xv.z, xv.w};
#pragma unroll
        for (int d = 0; d < 4; d++)
#pragma unroll
            for (int c = 0; c < H1D; c++)
                h[c] += xs[d] * w[(q * 4 + d) * H1D + c];
    }
    float f1 = 0.f, f2 = 0.f;
#pragma unroll
    for (int c = 0; c < H1D; c++) { f1 += h[c] * a[c]; f2 += h[c] * a[H1D + c]; }
    g_h1[kn] = make_float4(h[0], h[1], h[2], h[3]);
    g_f1p1[kn] = make_float2(__expf(f1), __expf(0.01f * f1));
    g_f2p1[kn] = make_float2(__expf(f2), __expf(0.01f * f2));
}

// ---------------- 3. attention kernel (templated on layer) ----------------
// F4==1: layer1 (h width 4), F4==2: layer2 (h width 8)
template <int F4>
__global__ void attn_kernel() {
    constexpr int F = 4 * F4;
    constexpr int RPW = 4;   // rows per warp
    __shared__ float4 hs[NN * F4];
    __shared__ float2 fs[NN];

    const float4* hmat = (F4 == 1) ? g_h1 : g_h2;
    const float2* f1p  = (F4 == 1) ? g_f1p1 : g_f1p2;
    const float2* f2p  = (F4 == 1) ? g_f2p1 : g_f2p2;
    float4* outv       = (F4 == 1) ? g_h1o : g_g4;

    int k = blockIdx.y;
    int tid = threadIdx.x;
    const float4* hk = hmat + k * NN * F4;
    for (int idx = tid; idx < NN * F4; idx += 256) hs[idx] = hk[idx];
    const float2* fk = f2p + k * NN;
    for (int idx = tid; idx < NN; idx += 256) fs[idx] = fk[idx];
    __syncthreads();

    int warp = tid >> 5, lane = tid & 31;
    int i0 = blockIdx.x * (8 * RPW) + warp * RPW;

    float2 e1[RPW];
    unsigned tw[RPW];
    float z[RPW];
    float acc[RPW][F];
#pragma unroll
    for (int r = 0; r < RPW; r++) {
        e1[r] = f1p[k * NN + i0 + r];
        tw[r] = g_adjT[(i0 + r) * 32 + lane];
        z[r] = 0.f;
#pragma unroll
        for (int f = 0; f < F; f++) acc[r][f] = 0.f;
    }

#pragma unroll 8
    for (int jj = 0; jj < 32; jj++) {
        int j = jj * 32 + lane;
        float2 ef = fs[j];
        float4 hv0 = hs[j * F4];
        float4 hv1;
        if (F4 == 2) hv1 = hs[j * F4 + 1];
#pragma unroll
        for (int r = 0; r < RPW; r++) {
            float A = e1[r].x * ef.x;
            float B = e1[r].y * ef.y;
            float p = fmaxf(A, B);                       // = exp(leaky_relu(f1+f2))
            int m = ((int)(tw[r] << (31 - jj))) >> 31;   // all-ones if adjacent
            p = __uint_as_float(__float_as_uint(p) & (unsigned)m);
            z[r] += p;
            acc[r][0] += p * hv0.x;
            acc[r][1] += p * hv0.y;
            acc[r][2] += p * hv0.z;
            acc[r][3] += p * hv0.w;
            if (F4 == 2) {
                acc[r][4] += p * hv1.x;
                acc[r][5] += p * hv1.y;
                acc[r][6] += p * hv1.z;
                acc[r][7] += p * hv1.w;
            }
        }
    }

    // warp reductions + write
#pragma unroll
    for (int r = 0; r < RPW; r++) {
#pragma unroll
        for (int o = 16; o; o >>= 1) {
            z[r] += __shfl_xor_sync(0xffffffffu, z[r], o);
#pragma unroll
            for (int f = 0; f < F; f++)
                acc[r][f] += __shfl_xor_sync(0xffffffffu, acc[r][f], o);
        }
        if (lane == 0) {
            float invz = (z[r] > 0.f) ? 1.f / z[r] : 0.f;
            int i = i0 + r;
            float4 o0 = make_float4(fmaxf(acc[r][0] * invz, 0.f), fmaxf(acc[r][1] * invz, 0.f),
                                    fmaxf(acc[r][2] * invz, 0.f), fmaxf(acc[r][3] * invz, 0.f));
            outv[(k * NN + i) * F4] = o0;
            if (F4 == 2) {
                float4 o1 = make_float4(fmaxf(acc[r][4] * invz, 0.f), fmaxf(acc[r][5] * invz, 0.f),
                                        fmaxf(acc[r][6] * invz, 0.f), fmaxf(acc[r][7] * invz, 0.f));
                outv[(k * NN + i) * F4 + 1] = o1;
            }
        }
    }
}

// ---------------- 4. layer-2 projection + exp precompute ----------------
__global__ void prep2_kernel(const float* __restrict__ W2,
                             const float* __restrict__ a2) {
    __shared__ float w[H1D * DOUT];
    __shared__ float a[2 * DOUT];
    int t = threadIdx.x;
    if (t < H1D * DOUT) w[t] = W2[t];
    if (t < 2 * DOUT) a[t] = a2[t];
    __syncthreads();
    int kn = blockIdx.x * 256 + t;
    float4 v = g_h1o[kn];
    float hv[4] = {v.x, v.y, v.z, v.w};
    float h[DOUT];
#pragma unroll
    for (int o = 0; o < DOUT; o++) {
        float s = 0.f;
#pragma unroll
        for (int f = 0; f < H1D; f++) s += hv[f] * w[f * DOUT + o];
        h[o] = s;
    }
    float f1 = 0.f, f2 = 0.f;
#pragma unroll
    for (int o = 0; o < DOUT; o++) { f1 += h[o] * a[o]; f2 += h[o] * a[DOUT + o]; }
    g_h2[kn * 2]     = make_float4(h[0], h[1], h[2], h[3]);
    g_h2[kn * 2 + 1] = make_float4(h[4], h[5], h[6], h[7]);
    g_f1p2[kn] = make_float2(__expf(f1), __expf(0.01f * f1));
    g_f2p2[kn] = make_float2(__expf(f2), __expf(0.01f * f2));
}

// ---------------- 5. head ----------------
__global__ void zero_x_kernel() {
    int t = blockIdx.x * 256 + threadIdx.x;
    if (t < KBATCH * FC1D) g_x[t] = 0.f;
}

#define DCHUNK 128
__global__ void head_fc1_kernel(const float* __restrict__ fc1w) {
    __shared__ float ws[FC1D * (DCHUNK + 4)];  // transposed [c][r]
    int t = threadIdx.x;
    int d0 = blockIdx.x * DCHUNK;
    for (int idx = t; idx < DCHUNK * FC1D; idx += 256) {
        int r = idx / FC1D, c = idx % FC1D;
        ws[c * (DCHUNK + 4) + r] = fc1w[d0 * FC1D + idx];
    }
    __syncthreads();
    int warp = t >> 5, lane = t & 31;
    const float* gg = reinterpret_cast<const float*>(g_g4);
    for (int k = warp; k < KBATCH; k += 8) {
        float gv[DCHUNK / 32];
#pragma unroll
        for (int m = 0; m < DCHUNK / 32; m++)
            gv[m] = gg[k * (NN * DOUT) + d0 + lane + 32 * m];
        for (int c = 0; c < FC1D; c++) {
            float s = 0.f;
#pragma unroll
            for (int m = 0; m < DCHUNK / 32; m++)
                s += gv[m] * ws[c * (DCHUNK + 4) + lane + 32 * m];
#pragma unroll
            for (int o = 16; o; o >>= 1) s += __shfl_xor_sync(0xffffffffu, s, o);
            if (lane == 0) atomicAdd(&g_x[k * FC1D + c], s);
        }
    }
}

__global__ void head_out_kernel(const float* __restrict__ fc1b,
                                const float* __restrict__ outw,
                                const float* __restrict__ outb,
                                float* __restrict__ out) {
    __shared__ float xs[FC1D];
    int k = blockIdx.y;
    int t = threadIdx.x;
    if (t < FC1D) xs[t] = fmaxf(g_x[k * FC1D + t] + fc1b[t], 0.f);
    __syncthreads();
    int n = blockIdx.x * 256 + t;
    float s = outb[n];
#pragma unroll
    for (int c = 0; c < FC1D; c++) s += xs[c] * outw[c * NN + n];
    out[k * NN + n] = s;
}

// ---------------- launch ----------------
extern "C" void kernel_launch(void* const* d_in, const int* in_sizes, int n_in,
                              void* d_out, int out_size) {
    const float* X    = (const float*)d_in[0];
    const int*   adj  = (const int*)d_in[1];
    const float* W1   = (const float*)d_in[2];
    const float* a1   = (const float*)d_in[3];
    const float* W2   = (const float*)d_in[4];
    const float* a2   = (const float*)d_in[5];
    const float* fc1w = (const float*)d_in[6];
    const float* fc1b = (const float*)d_in[7];
    const float* outw = (const float*)d_in[8];
    const float* outb = (const float*)d_in[9];
    float* out = (float*)d_out;

    pack_adj_kernel<<<NN / 8, 256>>>(adj);
    zero_x_kernel<<<14, 256>>>();
    prep1_kernel<<<KBATCH * NN / 256, 256>>>(X, W1, a1);
    {
        dim3 grid(NN / 32, KBATCH);
        attn_kernel<1><<<grid, 256>>>();
    }
    prep2_kernel<<<KBATCH * NN / 256, 256>>>(W2, a2);
    {
        dim3 grid(NN / 32, KBATCH);
        attn_kernel<2><<<grid, 256>>>();
    }
    head_fc1_kernel<<<(NN * DOUT) / DCHUNK, 256>>>(fc1w);
    {
        dim3 grid(NN / 256, KBATCH);
        head_out_kernel<<<grid, 256>>>(fc1b, outw, outb, out);
    }
}

// round 2
// speedup vs baseline: 1.1591x; 1.1591x over previous
#include <cuda_runtime.h>

#define KBATCH 64
#define NN 1024
#define DIN 16
#define H1D 4
#define DOUT 8
#define FC1D 54

typedef unsigned long long ull;

// ---------------- scratch (static device memory) ----------------
__device__ unsigned g_adjT[NN * 32];            // word (i,l) bit jj = adj[i][jj*32+l]
__device__ ull g_h1q[2 * KBATCH * NN];          // layer1 h pairs, SoA: [q][k*N+n]
__device__ ull g_h2q[4 * KBATCH * NN];          // layer2 h pairs, SoA
__device__ ull g_f1p1[KBATCH * NN];             // {e^f1, e^{0.01 f1}}
__device__ ull g_f2p1[KBATCH * NN];
__device__ ull g_f1p2[KBATCH * NN];
__device__ ull g_f2p2[KBATCH * NN];
__device__ ull g_g4[KBATCH * NN * 4];           // relu(gat2) pairs == [K][8192] floats
__device__ float g_x[KBATCH * FC1D];

// ---------------- f32x2 helpers ----------------
__device__ __forceinline__ ull mul2(ull a, ull b) {
    ull r; asm("mul.rn.f32x2 %0,%1,%2;" : "=l"(r) : "l"(a), "l"(b)); return r;
}
__device__ __forceinline__ ull fma2(ull a, ull b, ull c) {
    ull r; asm("fma.rn.f32x2 %0,%1,%2,%3;" : "=l"(r) : "l"(a), "l"(b), "l"(c)); return r;
}
__device__ __forceinline__ ull add2(ull a, ull b) {
    ull r; asm("add.rn.f32x2 %0,%1,%2;" : "=l"(r) : "l"(a), "l"(b)); return r;
}
__device__ __forceinline__ float lo2(ull v) { return __uint_as_float((unsigned)v); }
__device__ __forceinline__ float hi2(ull v) { return __uint_as_float((unsigned)(v >> 32)); }
__device__ __forceinline__ ull pk(float x, float y) {
    return (ull)__float_as_uint(x) | ((ull)__float_as_uint(y) << 32);
}
__device__ __forceinline__ ull shfl2(ull v, int o) {
    unsigned l = (unsigned)v, h = (unsigned)(v >> 32);
    l = __shfl_xor_sync(0xffffffffu, l, o);
    h = __shfl_xor_sync(0xffffffffu, h, o);
    return (ull)l | ((ull)h << 32);
}

// ---------------- prologue: pack adj + prep1 + zero ----------------
__global__ void prologue_kernel(const int* __restrict__ adj,
                                const float* __restrict__ X,
                                const float* __restrict__ W1,
                                const float* __restrict__ a1) {
    __shared__ float w[DIN * H1D];
    __shared__ float a[2 * H1D];
    int b = blockIdx.x, t = threadIdx.x;
    if (b < 128) {
        int warp = t >> 5, lane = t & 31;
        int i = b * 8 + warp;
        unsigned acc = 0;
#pragma unroll
        for (int jj = 0; jj < 32; jj++) {
            int v = adj[i * NN + jj * 32 + lane];
            acc |= (v > 0 ? 1u : 0u) << jj;
        }
        g_adjT[i * 32 + lane] = acc;
    } else if (b < 384) {
        if (t < DIN * H1D) w[t] = W1[t];
        if (t < 2 * H1D) a[t] = a1[t];
        __syncthreads();
        int kn = (b - 128) * 256 + t;
        const float4* x4 = reinterpret_cast<const float4*>(X) + kn * 4;
        float h[H1D] = {0.f, 0.f, 0.f, 0.f};
#pragma unroll
        for (int q = 0; q < 4; q++) {
            float4 xv = x4[q];
            float xs[4] = {xv.x, xv.y, xv.z, xv.w};
#pragma unroll
            for (int d = 0; d < 4; d++)
#pragma unroll
                for (int c = 0; c < H1D; c++)
                    h[c] += xs[d] * w[(q * 4 + d) * H1D + c];
        }
        float f1 = 0.f, f2 = 0.f;
#pragma unroll
        for (int c = 0; c < H1D; c++) { f1 += h[c] * a[c]; f2 += h[c] * a[H1D + c]; }
        g_h1q[kn] = pk(h[0], h[1]);
        g_h1q[KBATCH * NN + kn] = pk(h[2], h[3]);
        g_f1p1[kn] = pk(__expf(f1), __expf(0.01f * f1));
        g_f2p1[kn] = pk(__expf(f2), __expf(0.01f * f2));
    } else {
        for (int i = t; i < KBATCH * FC1D; i += 256) g_x[i] = 0.f;
    }
}

// ---------------- attention (layer templated); layer1 fuses prep2 epilogue ----------------
template <int LAYER>
__global__ void __launch_bounds__(256, 3) attn_kernel(const float* __restrict__ W2,
                                                      const float* __restrict__ a2) {
    constexpr int NP = (LAYER == 1) ? 2 : 4;   // h pairs per node
    constexpr int RPW = 4;                      // rows per warp
    __shared__ ull fs[NN];
    __shared__ ull vs[NP][NN];
    __shared__ float w2s[H1D * DOUT + 2 * DOUT];

    const int k = blockIdx.y;
    const int tid = threadIdx.x;

    const ull* fk = (LAYER == 1 ? g_f2p1 : g_f2p2) + k * NN;
#pragma unroll
    for (int idx = tid; idx < NN; idx += 256) fs[idx] = fk[idx];
    const ull* hq = (LAYER == 1) ? g_h1q : g_h2q;
#pragma unroll
    for (int idx = tid; idx < NN * NP; idx += 256) {
        int q = idx >> 10, j = idx & (NN - 1);
        vs[q][j] = hq[q * (KBATCH * NN) + k * NN + j];
    }
    if (LAYER == 1 && tid < H1D * DOUT + 2 * DOUT)
        w2s[tid] = (tid < H1D * DOUT) ? W2[tid] : a2[tid - H1D * DOUT];
    __syncthreads();

    const int warp = tid >> 5, lane = tid & 31;
    const int i0 = blockIdx.x * (8 * RPW) + warp * RPW;

    ull e1[RPW];
    unsigned tw[RPW];
    float z[RPW];
    ull acc[RPW][NP];
    const ull* f1u = (LAYER == 1) ? g_f1p1 : g_f1p2;
#pragma unroll
    for (int r = 0; r < RPW; r++) {
        e1[r] = f1u[k * NN + i0 + r];
        tw[r] = g_adjT[(i0 + r) * 32 + lane];
        z[r] = 0.f;
#pragma unroll
        for (int q = 0; q < NP; q++) acc[r][q] = 0ull;
    }

#pragma unroll 8
    for (int jj = 0; jj < 32; jj++) {
        ull ef = fs[jj * 32 + lane];
        ull hv[NP];
#pragma unroll
        for (int q = 0; q < NP; q++) hv[q] = vs[q][jj * 32 + lane];
#pragma unroll
        for (int r = 0; r < RPW; r++) {
            ull ab = mul2(e1[r], ef);
            float p = fmaxf(lo2(ab), hi2(ab));            // exp(leaky_relu(f1+f2))
            unsigned m = (unsigned)(((int)(tw[r] << (31 - jj))) >> 31);
            unsigned pu = __float_as_uint(p) & m;
            ull pp;
            asm("mov.b64 %0,{%1,%1};" : "=l"(pp) : "r"(pu));
            z[r] += __uint_as_float(pu);
#pragma unroll
            for (int q = 0; q < NP; q++) acc[r][q] = fma2(pp, hv[q], acc[r][q]);
        }
    }

    // butterfly reductions
#pragma unroll
    for (int r = 0; r < RPW; r++) {
#pragma unroll
        for (int o = 16; o; o >>= 1) {
            z[r] += __shfl_xor_sync(0xffffffffu, z[r], o);
#pragma unroll
            for (int q = 0; q < NP; q++) acc[r][q] = add2(acc[r][q], shfl2(acc[r][q], o));
        }
    }

    if (lane < RPW) {
        ull A[NP]; float Z;
#pragma unroll
        for (int r = 0; r < RPW; r++)
            if (lane == r) {
                Z = z[r];
#pragma unroll
                for (int q = 0; q < NP; q++) A[q] = acc[r][q];
            }
        float invz = (Z > 0.f) ? 1.f / Z : 0.f;
        int gi = k * NN + i0 + lane;
        if (LAYER == 1) {
            float h0 = fmaxf(lo2(A[0]) * invz, 0.f);
            float h1 = fmaxf(hi2(A[0]) * invz, 0.f);
            float h2 = fmaxf(lo2(A[1]) * invz, 0.f);
            float h3 = fmaxf(hi2(A[1]) * invz, 0.f);
            float hh[DOUT];
#pragma unroll
            for (int o = 0; o < DOUT; o++)
                hh[o] = h0 * w2s[o] + h1 * w2s[DOUT + o] + h2 * w2s[2 * DOUT + o] + h3 * w2s[3 * DOUT + o];
            float f1 = 0.f, f2 = 0.f;
#pragma unroll
            for (int o = 0; o < DOUT; o++) {
                f1 += hh[o] * w2s[H1D * DOUT + o];
                f2 += hh[o] * w2s[H1D * DOUT + DOUT + o];
            }
#pragma unroll
            for (int q = 0; q < 4; q++)
                g_h2q[q * (KBATCH * NN) + gi] = pk(hh[2 * q], hh[2 * q + 1]);
            g_f1p2[gi] = pk(__expf(f1), __expf(0.01f * f1));
            g_f2p2[gi] = pk(__expf(f2), __expf(0.01f * f2));
        } else {
#pragma unroll
            for (int q = 0; q < NP; q++)
                g_g4[gi * 4 + q] = pk(fmaxf(lo2(A[q]) * invz, 0.f),
                                      fmaxf(hi2(A[q]) * invz, 0.f));
        }
    }
}

// ---------------- head ----------------
#define DCHUNK 128
__global__ void head_fc1_kernel(const float* __restrict__ fc1w) {
    __shared__ float ws[FC1D * (DCHUNK + 4)];
    int t = threadIdx.x;
    int d0 = blockIdx.x * DCHUNK;
    for (int idx = t; idx < DCHUNK * FC1D; idx += 256) {
        int r = idx / FC1D, c = idx % FC1D;
        ws[c * (DCHUNK + 4) + r] = fc1w[d0 * FC1D + idx];
    }
    __syncthreads();
    int warp = t >> 5, lane = t & 31;
    const float* gg = reinterpret_cast<const float*>(g_g4);
    for (int k = warp; k < KBATCH; k += 8) {
        float gv[DCHUNK / 32];
#pragma unroll
        for (int m = 0; m < DCHUNK / 32; m++)
            gv[m] = gg[k * (NN * DOUT) + d0 + lane + 32 * m];
        for (int c = 0; c < FC1D; c++) {
            float s = 0.f;
#pragma unroll
            for (int m = 0; m < DCHUNK / 32; m++)
                s += gv[m] * ws[c * (DCHUNK + 4) + lane + 32 * m];
#pragma unroll
            for (int o = 16; o; o >>= 1) s += __shfl_xor_sync(0xffffffffu, s, o);
            if (lane == 0) atomicAdd(&g_x[k * FC1D + c], s);
        }
    }
}

__global__ void head_out_kernel(const float* __restrict__ fc1b,
                                const float* __restrict__ outw,
                                const float* __restrict__ outb,
                                float* __restrict__ out) {
    __shared__ float xs[FC1D];
    int k = blockIdx.y;
    int t = threadIdx.x;
    if (t < FC1D) xs[t] = fmaxf(g_x[k * FC1D + t] + fc1b[t], 0.f);
    __syncthreads();
    int n = blockIdx.x * 256 + t;
    float s = outb[n];
#pragma unroll
    for (int c = 0; c < FC1D; c++) s += xs[c] * outw[c * NN + n];
    out[k * NN + n] = s;
}

// ---------------- launch ----------------
extern "C" void kernel_launch(void* const* d_in, const int* in_sizes, int n_in,
                              void* d_out, int out_size) {
    const float* X    = (const float*)d_in[0];
    const int*   adj  = (const int*)d_in[1];
    const float* W1   = (const float*)d_in[2];
    const float* a1   = (const float*)d_in[3];
    const float* W2   = (const float*)d_in[4];
    const float* a2   = (const float*)d_in[5];
    const float* fc1w = (const float*)d_in[6];
    const float* fc1b = (const float*)d_in[7];
    const float* outw = (const float*)d_in[8];
    const float* outb = (const float*)d_in[9];
    float* out = (float*)d_out;

    prologue_kernel<<<385, 256>>>(adj, X, W1, a1);
    {
        dim3 grid(NN / 32, KBATCH);
        attn_kernel<1><<<grid, 256>>>(W2, a2);
        attn_kernel<2><<<grid, 256>>>(W2, a2);
    }
    head_fc1_kernel<<<(NN * DOUT) / DCHUNK, 256>>>(fc1w);
    {
        dim3 grid(NN / 256, KBATCH);
        head_out_kernel<<<grid, 256>>>(fc1b, outw, outb, out);
    }
}

// round 3
// speedup vs baseline: 1.5706x; 1.3549x over previous
#include <cuda_runtime.h>

#define KBATCH 64
#define NN 1024
#define DIN 16
#define H1D 4
#define DOUT 8
#define FC1D 54

typedef unsigned long long ull;

// ---------------- scratch (static device memory) ----------------
__device__ unsigned g_adjT[NN * 32];            // word (i,l) bit jj = adj[i][jj*32+l]
__device__ ull g_h1q[2 * KBATCH * NN];          // layer1 h pairs, SoA: [q][k*N+n]
__device__ ull g_h2q[4 * KBATCH * NN];          // layer2 h pairs, SoA
__device__ ull g_f1p1[KBATCH * NN];             // {e^f1, e^{0.01 f1}}
__device__ ull g_f2p1[KBATCH * NN];
__device__ ull g_f1p2[KBATCH * NN];
__device__ ull g_f2p2[KBATCH * NN];
__device__ ull g_g4[KBATCH * NN * 4];           // relu(gat2) pairs == [K][8192] floats
__device__ float g_x[KBATCH * FC1D];

// ---------------- f32x2 helpers ----------------
__device__ __forceinline__ ull mul2(ull a, ull b) {
    ull r; asm("mul.rn.f32x2 %0,%1,%2;" : "=l"(r) : "l"(a), "l"(b)); return r;
}
__device__ __forceinline__ ull fma2(ull a, ull b, ull c) {
    ull r; asm("fma.rn.f32x2 %0,%1,%2,%3;" : "=l"(r) : "l"(a), "l"(b), "l"(c)); return r;
}
__device__ __forceinline__ ull add2(ull a, ull b) {
    ull r; asm("add.rn.f32x2 %0,%1,%2;" : "=l"(r) : "l"(a), "l"(b)); return r;
}
__device__ __forceinline__ float lo2(ull v) { return __uint_as_float((unsigned)v); }
__device__ __forceinline__ float hi2(ull v) { return __uint_as_float((unsigned)(v >> 32)); }
__device__ __forceinline__ ull pk(float x, float y) {
    return (ull)__float_as_uint(x) | ((ull)__float_as_uint(y) << 32);
}
__device__ __forceinline__ ull bcast2(unsigned v) {
    ull r; asm("mov.b64 %0,{%1,%1};" : "=l"(r) : "r"(v)); return r;
}
__device__ __forceinline__ ull shfl2(ull v, int o) {
    unsigned l = (unsigned)v, h = (unsigned)(v >> 32);
    l = __shfl_xor_sync(0xffffffffu, l, o);
    h = __shfl_xor_sync(0xffffffffu, h, o);
    return (ull)l | ((ull)h << 32);
}

// ---------------- prologue: pack adj + prep1 + zero ----------------
__global__ void prologue_kernel(const int* __restrict__ adj,
                                const float* __restrict__ X,
                                const float* __restrict__ W1,
                                const float* __restrict__ a1) {
    __shared__ float w[DIN * H1D];
    __shared__ float a[2 * H1D];
    int b = blockIdx.x, t = threadIdx.x;
    if (b < 128) {
        int warp = t >> 5, lane = t & 31;
        int i = b * 8 + warp;
        unsigned acc = 0;
#pragma unroll
        for (int jj = 0; jj < 32; jj++) {
            int v = adj[i * NN + jj * 32 + lane];
            acc |= (v > 0 ? 1u : 0u) << jj;
        }
        g_adjT[i * 32 + lane] = acc;
    } else if (b < 384) {
        if (t < DIN * H1D) w[t] = W1[t];
        if (t < 2 * H1D) a[t] = a1[t];
        __syncthreads();
        int kn = (b - 128) * 256 + t;
        const float4* x4 = reinterpret_cast<const float4*>(X) + kn * 4;
        float h[H1D] = {0.f, 0.f, 0.f, 0.f};
#pragma unroll
        for (int q = 0; q < 4; q++) {
            float4 xv = x4[q];
            float xs[4] = {xv.x, xv.y, xv.z, xv.w};
#pragma unroll
            for (int d = 0; d < 4; d++)
#pragma unroll
                for (int c = 0; c < H1D; c++)
                    h[c] += xs[d] * w[(q * 4 + d) * H1D + c];
        }
        float f1 = 0.f, f2 = 0.f;
#pragma unroll
        for (int c = 0; c < H1D; c++) { f1 += h[c] * a[c]; f2 += h[c] * a[H1D + c]; }
        g_h1q[kn] = pk(h[0], h[1]);
        g_h1q[KBATCH * NN + kn] = pk(h[2], h[3]);
        g_f1p1[kn] = pk(__expf(f1), __expf(0.01f * f1));
        g_f2p1[kn] = pk(__expf(f2), __expf(0.01f * f2));
    } else {
        for (int i = t; i < KBATCH * FC1D; i += 256) g_x[i] = 0.f;
    }
}

// ---------------- attention (layer templated); layer1 fuses prep2 epilogue ----------------
template <int LAYER>
__global__ void __launch_bounds__(256, 3) attn_kernel(const float* __restrict__ W2,
                                                      const float* __restrict__ a2) {
    constexpr int NP = (LAYER == 1) ? 2 : 4;   // h pairs per node
    constexpr int RPW = 4;                      // rows per warp
    __shared__ ull fs[NN];
    __shared__ ull vs[NP][NN];
    __shared__ float w2s[H1D * DOUT + 2 * DOUT];

    const int k = blockIdx.y;
    const int tid = threadIdx.x;

    const ull* fk = (LAYER == 1 ? g_f2p1 : g_f2p2) + k * NN;
#pragma unroll
    for (int idx = tid; idx < NN; idx += 256) fs[idx] = fk[idx];
    const ull* hq = (LAYER == 1) ? g_h1q : g_h2q;
#pragma unroll
    for (int idx = tid; idx < NN * NP; idx += 256) {
        int q = idx >> 10, j = idx & (NN - 1);
        vs[q][j] = hq[q * (KBATCH * NN) + k * NN + j];
    }
    if (LAYER == 1 && tid < H1D * DOUT + 2 * DOUT)
        w2s[tid] = (tid < H1D * DOUT) ? W2[tid] : a2[tid - H1D * DOUT];
    __syncthreads();

    const int warp = tid >> 5, lane = tid & 31;
    const int i0 = blockIdx.x * (8 * RPW) + warp * RPW;

    ull e1[RPW];
    unsigned tw[RPW];
    float z[RPW];
    ull acc[RPW][NP];
    const ull* f1u = (LAYER == 1) ? g_f1p1 : g_f1p2;
#pragma unroll
    for (int r = 0; r < RPW; r++) {
        e1[r] = f1u[k * NN + i0 + r];
        tw[r] = g_adjT[(i0 + r) * 32 + lane];
        z[r] = 0.f;
#pragma unroll
        for (int q = 0; q < NP; q++) acc[r][q] = 0ull;
    }

#pragma unroll 8
    for (int jj = 0; jj < 32; jj++) {
        ull ef = fs[jj * 32 + lane];
        ull hv[NP];
#pragma unroll
        for (int q = 0; q < NP; q++) hv[q] = vs[q][jj * 32 + lane];
#pragma unroll
        for (int r = 0; r < RPW; r++) {
            ull ab = mul2(e1[r], ef);
            float p = fmaxf(lo2(ab), hi2(ab));            // exp(leaky_relu(f1+f2))
            unsigned m = (unsigned)(((int)(tw[r] << (31 - jj))) >> 31);
            unsigned pu = __float_as_uint(p) & m;
            ull pp = bcast2(pu);
            z[r] += __uint_as_float(pu);
#pragma unroll
            for (int q = 0; q < NP; q++) acc[r][q] = fma2(pp, hv[q], acc[r][q]);
        }
    }

    // butterfly reductions
#pragma unroll
    for (int r = 0; r < RPW; r++) {
#pragma unroll
        for (int o = 16; o; o >>= 1) {
            z[r] += __shfl_xor_sync(0xffffffffu, z[r], o);
#pragma unroll
            for (int q = 0; q < NP; q++) acc[r][q] = add2(acc[r][q], shfl2(acc[r][q], o));
        }
    }

    if (lane < RPW) {
        ull A[NP]; float Z;
#pragma unroll
        for (int r = 0; r < RPW; r++)
            if (lane == r) {
                Z = z[r];
#pragma unroll
                for (int q = 0; q < NP; q++) A[q] = acc[r][q];
            }
        float invz = (Z > 0.f) ? 1.f / Z : 0.f;
        int gi = k * NN + i0 + lane;
        if (LAYER == 1) {
            float h0 = fmaxf(lo2(A[0]) * invz, 0.f);
            float h1 = fmaxf(hi2(A[0]) * invz, 0.f);
            float h2 = fmaxf(lo2(A[1]) * invz, 0.f);
            float h3 = fmaxf(hi2(A[1]) * invz, 0.f);
            float hh[DOUT];
#pragma unroll
            for (int o = 0; o < DOUT; o++)
                hh[o] = h0 * w2s[o] + h1 * w2s[DOUT + o] + h2 * w2s[2 * DOUT + o] + h3 * w2s[3 * DOUT + o];
            float f1 = 0.f, f2 = 0.f;
#pragma unroll
            for (int o = 0; o < DOUT; o++) {
                f1 += hh[o] * w2s[H1D * DOUT + o];
                f2 += hh[o] * w2s[H1D * DOUT + DOUT + o];
            }
#pragma unroll
            for (int q = 0; q < 4; q++)
                g_h2q[q * (KBATCH * NN) + gi] = pk(hh[2 * q], hh[2 * q + 1]);
            g_f1p2[gi] = pk(__expf(f1), __expf(0.01f * f1));
            g_f2p2[gi] = pk(__expf(f2), __expf(0.01f * f2));
        } else {
#pragma unroll
            for (int q = 0; q < NP; q++)
                g_g4[gi * 4 + q] = pk(fmaxf(lo2(A[q]) * invz, 0.f),
                                      fmaxf(hi2(A[q]) * invz, 0.f));
        }
    }
}

// ---------------- head: fc1 as register-tiled split-K GEMM ----------------
#define FBLK 64
__global__ void __launch_bounds__(256) head_fc1_kernel(const float* __restrict__ fc1w) {
    __shared__ float gs[KBATCH][FBLK + 1];    // [k][d], pad 65 -> conflict-free column reads
    __shared__ float ws[FBLK][56];            // [d][c], row 224B (ull-aligned)
    const int t = threadIdx.x;
    const int d0 = blockIdx.x * FBLK;
    const float* gg = reinterpret_cast<const float*>(g_g4);

    // stage g tile: 64 k x 64 d (float4 global loads, coalesced)
    for (int idx = t; idx < KBATCH * (FBLK / 4); idx += 256) {
        int k = idx / (FBLK / 4), v = idx % (FBLK / 4);
        float4 x = *reinterpret_cast<const float4*>(gg + k * (NN * DOUT) + d0 + 4 * v);
        gs[k][4 * v + 0] = x.x; gs[k][4 * v + 1] = x.y;
        gs[k][4 * v + 2] = x.z; gs[k][4 * v + 3] = x.w;
    }
    // stage w tile: 64 d x 54 c
    for (int idx = t; idx < FBLK * FC1D; idx += 256) {
        int d = idx / FC1D, c = idx % FC1D;
        ws[d][c] = fc1w[(d0 + d) * FC1D + c];
    }
    __syncthreads();

    const int k = t & 63;       // warp = 32 consecutive k, same cg
    const int cg = t >> 6;      // 0..3 -> c base = cg*14 (covers 56 >= 54)
    ull acc[7] = {0ull, 0ull, 0ull, 0ull, 0ull, 0ull, 0ull};

#pragma unroll 4
    for (int d = 0; d < FBLK; d++) {
        ull g2 = bcast2(__float_as_uint(gs[k][d]));
        const ull* w2 = reinterpret_cast<const ull*>(&ws[d][cg * 14]);
#pragma unroll
        for (int q = 0; q < 7; q++) acc[q] = fma2(g2, w2[q], acc[q]);
    }

    const int cbase = cg * 14;
#pragma unroll
    for (int q = 0; q < 7; q++) {
        int c = cbase + 2 * q;
        if (c < FC1D)     atomicAdd(&g_x[k * FC1D + c], lo2(acc[q]));
        if (c + 1 < FC1D) atomicAdd(&g_x[k * FC1D + c + 1], hi2(acc[q]));
    }
}

__global__ void head_out_kernel(const float* __restrict__ fc1b,
                                const float* __restrict__ outw,
                                const float* __restrict__ outb,
                                float* __restrict__ out) {
    __shared__ float xs[FC1D];
    int k = blockIdx.y;
    int t = threadIdx.x;
    if (t < FC1D) xs[t] = fmaxf(g_x[k * FC1D + t] + fc1b[t], 0.f);
    __syncthreads();
    int n = blockIdx.x * 256 + t;
    float s = outb[n];
#pragma unroll
    for (int c = 0; c < FC1D; c++) s += xs[c] * outw[c * NN + n];
    out[k * NN + n] = s;
}

// ---------------- launch ----------------
extern "C" void kernel_launch(void* const* d_in, const int* in_sizes, int n_in,
                              void* d_out, int out_size) {
    const float* X    = (const float*)d_in[0];
    const int*   adj  = (const int*)d_in[1];
    const float* W1   = (const float*)d_in[2];
    const float* a1   = (const float*)d_in[3];
    const float* W2   = (const float*)d_in[4];
    const float* a2   = (const float*)d_in[5];
    const float* fc1w = (const float*)d_in[6];
    const float* fc1b = (const float*)d_in[7];
    const float* outw = (const float*)d_in[8];
    const float* outb = (const float*)d_in[9];
    float* out = (float*)d_out;

    prologue_kernel<<<385, 256>>>(adj, X, W1, a1);
    {
        dim3 grid(NN / 32, KBATCH);
        attn_kernel<1><<<grid, 256>>>(W2, a2);
        attn_kernel<2><<<grid, 256>>>(W2, a2);
    }
    head_fc1_kernel<<<(NN * DOUT) / FBLK, 256>>>(fc1w);
    {
        dim3 grid(NN / 256, KBATCH);
        head_out_kernel<<<grid, 256>>>(fc1b, outw, outb, out);
    }
}